// round 1
// baseline (speedup 1.0000x reference)
#include <cuda_runtime.h>

#define NB 4
#define NT 2048
#define ND 1024
#define NH 16
#define HD 64
#define QKV_N 3072
#define QPAD 65

// Scratch (static device globals — allocation-free at launch time)
__device__ float g_qkv[(size_t)NB * NT * QKV_N];  // [B*T, 3D]
__device__ float g_y[(size_t)NB * NT * ND];       // [B*T, D]

// ---------------------------------------------------------------------------
// Classic register-blocked SGEMM: C[M,N] = A[M,K] @ B[K,N], all row-major fp32.
// 128x128 block tile, BK=8, 8x8 per thread, 256 threads.
// M%128==0, N%128==0, K%8==0 guaranteed by problem shapes.
// ---------------------------------------------------------------------------
__global__ __launch_bounds__(256) void sgemm_kernel(
    const float* __restrict__ A, const float* __restrict__ Bm,
    float* __restrict__ C, int M, int N, int K)
{
    const int BM = 128, BN = 128, BK = 8;
    __shared__ float As[BK][BM];
    __shared__ float Bs[BK][BN];

    int tid  = threadIdx.x;
    int brow = blockIdx.y * BM;
    int bcol = blockIdx.x * BN;

    int a_row = tid >> 1;          // 0..127
    int a_col = (tid & 1) << 2;    // 0 or 4
    int b_row = tid >> 5;          // 0..7
    int b_col = (tid & 31) << 2;   // 0..124

    int tx = tid & 15, ty = tid >> 4;

    float acc[8][8] = {};

    const float* Aptr = A + (size_t)(brow + a_row) * K + a_col;
    const float* Bptr = Bm + (size_t)b_row * N + bcol + b_col;

    for (int k0 = 0; k0 < K; k0 += BK) {
        float4 av = *(const float4*)(Aptr + k0);
        As[a_col + 0][a_row] = av.x;
        As[a_col + 1][a_row] = av.y;
        As[a_col + 2][a_row] = av.z;
        As[a_col + 3][a_row] = av.w;
        float4 bv = *(const float4*)(Bptr + (size_t)k0 * N);
        *(float4*)&Bs[b_row][b_col] = bv;
        __syncthreads();

#pragma unroll
        for (int kk = 0; kk < BK; kk++) {
            float ra[8], rb[8];
            *(float4*)&ra[0] = *(const float4*)&As[kk][ty * 8];
            *(float4*)&ra[4] = *(const float4*)&As[kk][ty * 8 + 4];
            *(float4*)&rb[0] = *(const float4*)&Bs[kk][tx * 8];
            *(float4*)&rb[4] = *(const float4*)&Bs[kk][tx * 8 + 4];
#pragma unroll
            for (int i = 0; i < 8; i++)
#pragma unroll
                for (int j = 0; j < 8; j++)
                    acc[i][j] += ra[i] * rb[j];
        }
        __syncthreads();
    }

#pragma unroll
    for (int i = 0; i < 8; i++) {
        size_t r = (size_t)(brow + ty * 8 + i);
#pragma unroll
        for (int j = 0; j < 8; j += 4) {
            *(float4*)&C[r * N + bcol + tx * 8 + j] =
                make_float4(acc[i][j], acc[i][j + 1], acc[i][j + 2], acc[i][j + 3]);
        }
    }
}

// ---------------------------------------------------------------------------
// Flash-attention (fp32, causal). One block = one (b, h, 64-query tile).
// 64x64 S tiles, online softmax, causal tile pruning (j <= qtile).
// 256 threads; 4x4 register sub-tiles for S and O.
// Dynamic smem: Qs[64][65] + Ks[64][65] + Vs[64][64] + Ss[64][64] + m/l/alpha
// ---------------------------------------------------------------------------
__global__ __launch_bounds__(256) void attn_kernel(
    const float* __restrict__ qkv, float* __restrict__ y)
{
    extern __shared__ float sm[];
    float* Qs  = sm;                   // [64][QPAD]
    float* Ks  = Qs + 64 * QPAD;       // [64][QPAD]
    float* Vs  = Ks + 64 * QPAD;       // [64][64]
    float* Ss  = Vs + 64 * 64;         // [64][64]
    float* m_s = Ss + 64 * 64;         // [64]
    float* l_s = m_s + 64;             // [64]
    float* a_s = l_s + 64;             // [64]

    int tid   = threadIdx.x;
    int qtile = blockIdx.x;            // 0..31
    int bh    = blockIdx.y;            // 0..63
    int b = bh >> 4, h = bh & 15;
    int tx = tid & 15, ty = tid >> 4;
    const float scale = 0.125f;        // 1/sqrt(64)

    size_t base = (size_t)b * NT * QKV_N + (size_t)h * HD;

    // Load Q tile (64 rows x 64 dims), padded rows to kill bank conflicts
#pragma unroll
    for (int it = 0; it < 4; it++) {
        int r = (tid >> 4) + it * 16;
        int c = (tid & 15) << 2;
        float4 v = *(const float4*)&qkv[base + (size_t)(qtile * 64 + r) * QKV_N + c];
        Qs[r * QPAD + c + 0] = v.x;
        Qs[r * QPAD + c + 1] = v.y;
        Qs[r * QPAD + c + 2] = v.z;
        Qs[r * QPAD + c + 3] = v.w;
    }
    if (tid < 64) { m_s[tid] = -1e30f; l_s[tid] = 0.f; }

    float O[4][4] = {};

    for (int j = 0; j <= qtile; j++) {
        // Load K (padded) and V (row-major, float4) tiles
#pragma unroll
        for (int it = 0; it < 4; it++) {
            int r = (tid >> 4) + it * 16;
            int c = (tid & 15) << 2;
            size_t row = base + (size_t)(j * 64 + r) * QKV_N;
            float4 k4 = *(const float4*)&qkv[row + ND + c];
            Ks[r * QPAD + c + 0] = k4.x;
            Ks[r * QPAD + c + 1] = k4.y;
            Ks[r * QPAD + c + 2] = k4.z;
            Ks[r * QPAD + c + 3] = k4.w;
            float4 v4 = *(const float4*)&qkv[row + 2 * ND + c];
            *(float4*)&Vs[r * 64 + c] = v4;
        }
        __syncthreads();

        // S = Q K^T  (4x4 per thread, reduce over d)
        float s[4][4] = {};
#pragma unroll 8
        for (int d = 0; d < HD; d++) {
            float ra[4], rb[4];
#pragma unroll
            for (int i = 0; i < 4; i++)  ra[i] = Qs[(ty * 4 + i) * QPAD + d];
#pragma unroll
            for (int jj = 0; jj < 4; jj++) rb[jj] = Ks[(tx * 4 + jj) * QPAD + d];
#pragma unroll
            for (int i = 0; i < 4; i++)
#pragma unroll
                for (int jj = 0; jj < 4; jj++)
                    s[i][jj] += ra[i] * rb[jj];
        }

        // Scale + causal mask + store S tile
        int qg0 = qtile * 64 + ty * 4;
        int kg0 = j * 64 + tx * 4;
#pragma unroll
        for (int i = 0; i < 4; i++)
#pragma unroll
            for (int jj = 0; jj < 4; jj++) {
                float v = s[i][jj] * scale;
                if (kg0 + jj > qg0 + i) v = -1e30f;
                Ss[(ty * 4 + i) * 64 + tx * 4 + jj] = v;
            }
        __syncthreads();

        // Online softmax: one thread per row (rotated column order avoids
        // the 32-way same-bank pattern of straight row scans)
        if (tid < 64) {
            int r = tid;
            float mold = m_s[r];
            float mx = mold;
#pragma unroll 8
            for (int kk = 0; kk < 64; kk++)
                mx = fmaxf(mx, Ss[r * 64 + ((kk + r) & 63)]);
            float alpha = __expf(mold - mx);
            float sum = 0.f;
#pragma unroll 8
            for (int kk = 0; kk < 64; kk++) {
                int c = (kk + r) & 63;
                float p = __expf(Ss[r * 64 + c] - mx);
                Ss[r * 64 + c] = p;
                sum += p;
            }
            m_s[r] = mx;
            l_s[r] = l_s[r] * alpha + sum;
            a_s[r] = alpha;
        }
        __syncthreads();

        // Rescale O, then O += P @ V
        float al[4];
#pragma unroll
        for (int i = 0; i < 4; i++) al[i] = a_s[ty * 4 + i];
#pragma unroll
        for (int i = 0; i < 4; i++)
#pragma unroll
            for (int jj = 0; jj < 4; jj++)
                O[i][jj] *= al[i];

#pragma unroll 8
        for (int k = 0; k < 64; k++) {
            float pa[4];
#pragma unroll
            for (int i = 0; i < 4; i++) pa[i] = Ss[(ty * 4 + i) * 64 + k];
            float4 vb = *(const float4*)&Vs[k * 64 + tx * 4];
            float vf[4] = {vb.x, vb.y, vb.z, vb.w};
#pragma unroll
            for (int i = 0; i < 4; i++)
#pragma unroll
                for (int jj = 0; jj < 4; jj++)
                    O[i][jj] += pa[i] * vf[jj];
        }
        __syncthreads();
    }

    // Normalize and write y (head-interleaved [B*T, D] layout)
#pragma unroll
    for (int i = 0; i < 4; i++) {
        int q = ty * 4 + i;
        float inv = 1.0f / l_s[q];
        size_t row = ((size_t)b * NT + qtile * 64 + q) * ND + h * HD + tx * 4;
        *(float4*)&y[row] =
            make_float4(O[i][0] * inv, O[i][1] * inv, O[i][2] * inv, O[i][3] * inv);
    }
}

// ---------------------------------------------------------------------------
extern "C" void kernel_launch(void* const* d_in, const int* in_sizes, int n_in,
                              void* d_out, int out_size)
{
    const float* x     = (const float*)d_in[0];   // [B,T,D]
    const float* w_qkv = (const float*)d_in[1];   // [D, 3D]
    const float* w_out = (const float*)d_in[2];   // [D, D]
    float* out = (float*)d_out;                   // [B,T,D]

    float *qkv, *yb;
    cudaGetSymbolAddress((void**)&qkv, g_qkv);
    cudaGetSymbolAddress((void**)&yb, g_y);

    const int M = NB * NT;  // 8192

    // 1) qkv = x @ w_qkv
    sgemm_kernel<<<dim3(QKV_N / 128, M / 128), 256>>>(x, w_qkv, qkv, M, QKV_N, ND);

    // 2) causal flash attention -> y
    const int ATTN_SMEM = (64 * QPAD * 2 + 64 * 64 * 2 + 64 * 3) * (int)sizeof(float);
    cudaFuncSetAttribute(attn_kernel, cudaFuncAttributeMaxDynamicSharedMemorySize,
                         ATTN_SMEM);
    attn_kernel<<<dim3(NT / 64, NB * NH), 256, ATTN_SMEM>>>(qkv, yb);

    // 3) out = y @ w_out
    sgemm_kernel<<<dim3(ND / 128, M / 128), 256>>>(yb, w_out, out, M, ND, ND);
}

// round 3
// speedup vs baseline: 1.5376x; 1.5376x over previous
#include <cuda_runtime.h>
#include <cuda_bf16.h>
#include <cstdint>

#define NB 4
#define NT 2048
#define ND 1024
#define NH 16
#define HD 64
#define QKV_N 3072
#define QPAD 65

#define GM (NB * NT)   // 8192
#define GK 1024        // inner dim of both GEMMs
#define BK 64          // bf16 K per stage (128B rows)
#define KIT (GK / BK)  // 16
#define TILE_B 16384   // 128 rows x 128B
#define STAGE_B (4 * TILE_B)
#define GSMEM (2 * STAGE_B)

// ---------------- scratch (static device globals) ----------------
__device__ float g_qkv[(size_t)GM * QKV_N];
__device__ float g_y[(size_t)GM * ND];
__device__ __nv_bfloat16 g_ah[(size_t)GM * GK];
__device__ __nv_bfloat16 g_al[(size_t)GM * GK];
__device__ __nv_bfloat16 g_bh[(size_t)QKV_N * GK];
__device__ __nv_bfloat16 g_bl[(size_t)QKV_N * GK];

// ---------------- PTX helpers (sm_80+ portable; no 'a'-gated features) ------
__device__ __forceinline__ uint32_t smem_u32(const void* p) {
    uint32_t a;
    asm("{ .reg .u64 t; cvta.to.shared.u64 t, %1; cvt.u32.u64 %0, t; }"
        : "=r"(a) : "l"(p));
    return a;
}
__device__ __forceinline__ void cp_async16(uint32_t dst, const void* src) {
    asm volatile("cp.async.cg.shared.global [%0], [%1], 16;"
                 :: "r"(dst), "l"(src) : "memory");
}
__device__ __forceinline__ void cp_commit() {
    asm volatile("cp.async.commit_group;" ::: "memory");
}
template <int N>
__device__ __forceinline__ void cp_wait() {
    asm volatile("cp.async.wait_group %0;" :: "n"(N) : "memory");
}
__device__ __forceinline__ void ldsm_x4(uint32_t* r, uint32_t addr) {
    asm volatile("ldmatrix.sync.aligned.m8n8.x4.shared.b16 {%0,%1,%2,%3}, [%4];"
                 : "=r"(r[0]), "=r"(r[1]), "=r"(r[2]), "=r"(r[3]) : "r"(addr));
}
__device__ __forceinline__ void mma_bf16(float* c, const uint32_t* a,
                                         const uint32_t* b) {
    asm volatile(
        "mma.sync.aligned.m16n8k16.row.col.f32.bf16.bf16.f32 "
        "{%0,%1,%2,%3}, {%4,%5,%6,%7}, {%8,%9}, {%0,%1,%2,%3};"
        : "+f"(c[0]), "+f"(c[1]), "+f"(c[2]), "+f"(c[3])
        : "r"(a[0]), "r"(a[1]), "r"(a[2]), "r"(a[3]), "r"(b[0]), "r"(b[1]));
}
#define SWZ(x) ((uint32_t)(x) ^ ((((uint32_t)(x)) >> 3) & 0x70u))

// ---------------------------------------------------------------------------
// bf16x3 split GEMM via warp mma.sync: C = (Ah+Al) @ (Bh+Bl)^T, fp32 acc.
// CTA 128x128, BK=64, double-buffered cp.async, 8 warps (2m x 4n, warp 64x32).
// ---------------------------------------------------------------------------
__global__ __launch_bounds__(256) void gemm3_kernel(
    const __nv_bfloat16* __restrict__ Ah, const __nv_bfloat16* __restrict__ Al,
    const __nv_bfloat16* __restrict__ Bh, const __nv_bfloat16* __restrict__ Bl,
    float* __restrict__ C, int M, int N, int K)
{
    extern __shared__ char smem[];
    const uint32_t sbase = smem_u32(smem);
    const int tid = threadIdx.x;
    const int wid = tid >> 5;
    const int lane = tid & 31;

    const int brow = blockIdx.y * 128;
    const int bcol = blockIdx.x * 128;
    const int wr = wid >> 2;   // 0..1  (m group of 64)
    const int wc = wid & 3;    // 0..3  (n group of 32)

    // ---- global load mapping: 2 threads per 128B row, 4 x 16B each ----
    const int lrow = tid >> 1;          // 0..127
    const int lu4  = (tid & 1) * 4;     // 16B-unit base (0 or 4)

    const __nv_bfloat16* src[4];
    src[0] = Ah + (size_t)(brow + lrow) * K + lu4 * 8;
    src[1] = Al + (size_t)(brow + lrow) * K + lu4 * 8;
    src[2] = Bh + (size_t)(bcol + lrow) * K + lu4 * 8;
    src[3] = Bl + (size_t)(bcol + lrow) * K + lu4 * 8;

    uint32_t dsw[4];
#pragma unroll
    for (int q = 0; q < 4; q++)
        dsw[q] = SWZ(lrow * 128 + (lu4 + q) * 16);

    // ---- ldmatrix address offsets (within a tile) ----
    // A fragment (m16k16): rows = mi*16 + (lane&15), unit = ks*2 + (lane>>4)
    const int a_row_l = lane & 15;
    const int a_uoff  = lane >> 4;
    // B fragment pair (n16k16): n = np*16 + (lane&7) + ((lane>>4)&1)*8,
    //                           unit = ks*2 + ((lane>>3)&1)
    const int b_row_l = (lane & 7) + ((lane >> 4) & 1) * 8;
    const int b_uoff  = (lane >> 3) & 1;

    float acc[4][4][4] = {};  // [mfrag][nfrag][4]

    // ---- prologue: stage 0 ----
#pragma unroll
    for (int t = 0; t < 4; t++) {
        uint32_t dst = sbase + t * TILE_B;
#pragma unroll
        for (int q = 0; q < 4; q++)
            cp_async16(dst + dsw[q], src[t] + q * 8);
    }
    cp_commit();

    for (int it = 0; it < KIT; it++) {
        const int p = it & 1;
        if (it + 1 < KIT) {
            const uint32_t stg = sbase + (p ^ 1) * STAGE_B;
#pragma unroll
            for (int t = 0; t < 4; t++) {
                uint32_t dst = stg + t * TILE_B;
                const __nv_bfloat16* s = src[t] + (size_t)(it + 1) * BK;
#pragma unroll
                for (int q = 0; q < 4; q++)
                    cp_async16(dst + dsw[q], s + q * 8);
            }
            cp_commit();
            cp_wait<1>();
        } else {
            cp_wait<0>();
        }
        __syncthreads();

        const uint32_t sAh = sbase + p * STAGE_B;
        const uint32_t sAl = sAh + TILE_B;
        const uint32_t sBh = sAh + 2 * TILE_B;
        const uint32_t sBl = sAh + 3 * TILE_B;

#pragma unroll
        for (int ks = 0; ks < 4; ks++) {
            uint32_t ah[4][4], al[4][4];
#pragma unroll
            for (int mi = 0; mi < 4; mi++) {
                int row = wr * 64 + mi * 16 + a_row_l;
                uint32_t off = SWZ(row * 128 + (ks * 2 + a_uoff) * 16);
                ldsm_x4(ah[mi], sAh + off);
                ldsm_x4(al[mi], sAl + off);
            }
            uint32_t bh[4][2], bl[4][2];
#pragma unroll
            for (int np = 0; np < 2; np++) {
                int row = wc * 32 + np * 16 + b_row_l;
                uint32_t off = SWZ(row * 128 + (ks * 2 + b_uoff) * 16);
                uint32_t rh[4], rl[4];
                ldsm_x4(rh, sBh + off);
                ldsm_x4(rl, sBl + off);
                bh[np * 2][0] = rh[0]; bh[np * 2][1] = rh[1];
                bh[np * 2 + 1][0] = rh[2]; bh[np * 2 + 1][1] = rh[3];
                bl[np * 2][0] = rl[0]; bl[np * 2][1] = rl[1];
                bl[np * 2 + 1][0] = rl[2]; bl[np * 2 + 1][1] = rl[3];
            }
#pragma unroll
            for (int mi = 0; mi < 4; mi++)
#pragma unroll
                for (int ni = 0; ni < 4; ni++) {
                    mma_bf16(acc[mi][ni], ah[mi], bh[ni]);
                    mma_bf16(acc[mi][ni], ah[mi], bl[ni]);
                    mma_bf16(acc[mi][ni], al[mi], bh[ni]);
                }
        }
        __syncthreads();
    }

    // ---- epilogue ----
#pragma unroll
    for (int mi = 0; mi < 4; mi++) {
        int row0 = brow + wr * 64 + mi * 16 + (lane >> 2);
#pragma unroll
        for (int ni = 0; ni < 4; ni++) {
            int col = bcol + wc * 32 + ni * 8 + (lane & 3) * 2;
            float2* p0 = (float2*)&C[(size_t)row0 * N + col];
            float2* p1 = (float2*)&C[(size_t)(row0 + 8) * N + col];
            *p0 = make_float2(acc[mi][ni][0], acc[mi][ni][1]);
            *p1 = make_float2(acc[mi][ni][2], acc[mi][ni][3]);
        }
    }
}

// ---------------------------------------------------------------------------
// fp32 -> bf16 hi/lo split (elementwise, float4 vectorized)
// ---------------------------------------------------------------------------
__global__ __launch_bounds__(256) void split_kernel(
    const float* __restrict__ s, __nv_bfloat16* __restrict__ hi,
    __nv_bfloat16* __restrict__ lo, int n4)
{
    int i = blockIdx.x * 256 + threadIdx.x;
    if (i >= n4) return;
    float4 v = ((const float4*)s)[i];
    float f[4] = {v.x, v.y, v.z, v.w};
    __nv_bfloat16 h[4], l[4];
#pragma unroll
    for (int j = 0; j < 4; j++) {
        h[j] = __float2bfloat16(f[j]);
        l[j] = __float2bfloat16(f[j] - __bfloat162float(h[j]));
    }
    ((uint2*)hi)[i] = *(uint2*)h;
    ((uint2*)lo)[i] = *(uint2*)l;
}

// ---------------------------------------------------------------------------
// fp32 [K,N] -> bf16 hi/lo [N,K] split + transpose (32x32 smem tiles)
// ---------------------------------------------------------------------------
__global__ __launch_bounds__(256) void split_transpose_kernel(
    const float* __restrict__ src, __nv_bfloat16* __restrict__ hi,
    __nv_bfloat16* __restrict__ lo, int K, int N)
{
    __shared__ float t[32][33];
    int k0 = blockIdx.y * 32, n0 = blockIdx.x * 32;
    int tx = threadIdx.x & 31, ty = threadIdx.x >> 5;  // 32 x 8
#pragma unroll
    for (int i = 0; i < 32; i += 8)
        t[ty + i][tx] = src[(size_t)(k0 + ty + i) * N + n0 + tx];
    __syncthreads();
#pragma unroll
    for (int i = 0; i < 32; i += 8) {
        float v = t[tx][ty + i];
        __nv_bfloat16 h = __float2bfloat16(v);
        size_t o = (size_t)(n0 + ty + i) * K + k0 + tx;
        hi[o] = h;
        lo[o] = __float2bfloat16(v - __bfloat162float(h));
    }
}

// ---------------------------------------------------------------------------
// Flash-attention (fp32, causal) — unchanged from R1 (validated)
// ---------------------------------------------------------------------------
__global__ __launch_bounds__(256) void attn_kernel(
    const float* __restrict__ qkv, float* __restrict__ y)
{
    extern __shared__ float sm[];
    float* Qs  = sm;
    float* Ks  = Qs + 64 * QPAD;
    float* Vs  = Ks + 64 * QPAD;
    float* Ss  = Vs + 64 * 64;
    float* m_s = Ss + 64 * 64;
    float* l_s = m_s + 64;
    float* a_s = l_s + 64;

    int tid   = threadIdx.x;
    int qtile = blockIdx.x;
    int bh    = blockIdx.y;
    int b = bh >> 4, h = bh & 15;
    int tx = tid & 15, ty = tid >> 4;
    const float scale = 0.125f;

    size_t base = (size_t)b * NT * QKV_N + (size_t)h * HD;

#pragma unroll
    for (int it = 0; it < 4; it++) {
        int r = (tid >> 4) + it * 16;
        int c = (tid & 15) << 2;
        float4 v = *(const float4*)&qkv[base + (size_t)(qtile * 64 + r) * QKV_N + c];
        Qs[r * QPAD + c + 0] = v.x;
        Qs[r * QPAD + c + 1] = v.y;
        Qs[r * QPAD + c + 2] = v.z;
        Qs[r * QPAD + c + 3] = v.w;
    }
    if (tid < 64) { m_s[tid] = -1e30f; l_s[tid] = 0.f; }

    float O[4][4] = {};

    for (int j = 0; j <= qtile; j++) {
#pragma unroll
        for (int it = 0; it < 4; it++) {
            int r = (tid >> 4) + it * 16;
            int c = (tid & 15) << 2;
            size_t row = base + (size_t)(j * 64 + r) * QKV_N;
            float4 k4 = *(const float4*)&qkv[row + ND + c];
            Ks[r * QPAD + c + 0] = k4.x;
            Ks[r * QPAD + c + 1] = k4.y;
            Ks[r * QPAD + c + 2] = k4.z;
            Ks[r * QPAD + c + 3] = k4.w;
            float4 v4 = *(const float4*)&qkv[row + 2 * ND + c];
            *(float4*)&Vs[r * 64 + c] = v4;
        }
        __syncthreads();

        float s[4][4] = {};
#pragma unroll 8
        for (int d = 0; d < HD; d++) {
            float ra[4], rb[4];
#pragma unroll
            for (int i = 0; i < 4; i++)  ra[i] = Qs[(ty * 4 + i) * QPAD + d];
#pragma unroll
            for (int jj = 0; jj < 4; jj++) rb[jj] = Ks[(tx * 4 + jj) * QPAD + d];
#pragma unroll
            for (int i = 0; i < 4; i++)
#pragma unroll
                for (int jj = 0; jj < 4; jj++)
                    s[i][jj] += ra[i] * rb[jj];
        }

        int qg0 = qtile * 64 + ty * 4;
        int kg0 = j * 64 + tx * 4;
#pragma unroll
        for (int i = 0; i < 4; i++)
#pragma unroll
            for (int jj = 0; jj < 4; jj++) {
                float v = s[i][jj] * scale;
                if (kg0 + jj > qg0 + i) v = -1e30f;
                Ss[(ty * 4 + i) * 64 + tx * 4 + jj] = v;
            }
        __syncthreads();

        if (tid < 64) {
            int r = tid;
            float mold = m_s[r];
            float mx = mold;
#pragma unroll 8
            for (int kk = 0; kk < 64; kk++)
                mx = fmaxf(mx, Ss[r * 64 + ((kk + r) & 63)]);
            float alpha = __expf(mold - mx);
            float sum = 0.f;
#pragma unroll 8
            for (int kk = 0; kk < 64; kk++) {
                int c = (kk + r) & 63;
                float p = __expf(Ss[r * 64 + c] - mx);
                Ss[r * 64 + c] = p;
                sum += p;
            }
            m_s[r] = mx;
            l_s[r] = l_s[r] * alpha + sum;
            a_s[r] = alpha;
        }
        __syncthreads();

        float al[4];
#pragma unroll
        for (int i = 0; i < 4; i++) al[i] = a_s[ty * 4 + i];
#pragma unroll
        for (int i = 0; i < 4; i++)
#pragma unroll
            for (int jj = 0; jj < 4; jj++)
                O[i][jj] *= al[i];

#pragma unroll 8
        for (int k = 0; k < 64; k++) {
            float pa[4];
#pragma unroll
            for (int i = 0; i < 4; i++) pa[i] = Ss[(ty * 4 + i) * 64 + k];
            float4 vb = *(const float4*)&Vs[k * 64 + tx * 4];
            float vf[4] = {vb.x, vb.y, vb.z, vb.w};
#pragma unroll
            for (int i = 0; i < 4; i++)
#pragma unroll
                for (int jj = 0; jj < 4; jj++)
                    O[i][jj] += pa[i] * vf[jj];
        }
        __syncthreads();
    }

#pragma unroll
    for (int i = 0; i < 4; i++) {
        int q = ty * 4 + i;
        float inv = 1.0f / l_s[q];
        size_t row = ((size_t)b * NT + qtile * 64 + q) * ND + h * HD + tx * 4;
        *(float4*)&y[row] =
            make_float4(O[i][0] * inv, O[i][1] * inv, O[i][2] * inv, O[i][3] * inv);
    }
}

// ---------------------------------------------------------------------------
extern "C" void kernel_launch(void* const* d_in, const int* in_sizes, int n_in,
                              void* d_out, int out_size)
{
    const float* x     = (const float*)d_in[0];
    const float* w_qkv = (const float*)d_in[1];
    const float* w_out = (const float*)d_in[2];
    float* out = (float*)d_out;

    float *qkv, *yb;
    __nv_bfloat16 *ah, *al, *bh, *bl;
    cudaGetSymbolAddress((void**)&qkv, g_qkv);
    cudaGetSymbolAddress((void**)&yb, g_y);
    cudaGetSymbolAddress((void**)&ah, g_ah);
    cudaGetSymbolAddress((void**)&al, g_al);
    cudaGetSymbolAddress((void**)&bh, g_bh);
    cudaGetSymbolAddress((void**)&bl, g_bl);

    cudaFuncSetAttribute(gemm3_kernel, cudaFuncAttributeMaxDynamicSharedMemorySize,
                         GSMEM);
    const int ATTN_SMEM = (64 * QPAD * 2 + 64 * 64 * 2 + 64 * 3) * (int)sizeof(float);
    cudaFuncSetAttribute(attn_kernel, cudaFuncAttributeMaxDynamicSharedMemorySize,
                         ATTN_SMEM);

    const int n4 = GM * GK / 4;

    // 1) split x, split+transpose w_qkv
    split_kernel<<<(n4 + 255) / 256, 256>>>(x, ah, al, n4);
    split_transpose_kernel<<<dim3(QKV_N / 32, GK / 32), 256>>>(w_qkv, bh, bl, GK, QKV_N);

    // 2) qkv = x @ w_qkv  (bf16x3 mma.sync)
    gemm3_kernel<<<dim3(QKV_N / 128, GM / 128), 256, GSMEM>>>(
        ah, al, bh, bl, qkv, GM, QKV_N, GK);

    // 3) causal flash attention -> y
    attn_kernel<<<dim3(NT / 64, NB * NH), 256, ATTN_SMEM>>>(qkv, yb);

    // 4) split y, split+transpose w_out
    split_kernel<<<(n4 + 255) / 256, 256>>>(yb, ah, al, n4);
    split_transpose_kernel<<<dim3(ND / 32, GK / 32), 256>>>(w_out, bh, bl, GK, ND);

    // 5) out = y @ w_out  (bf16x3 mma.sync)
    gemm3_kernel<<<dim3(ND / 128, GM / 128), 256, GSMEM>>>(
        ah, al, bh, bl, out, GM, ND, GK);
}

// round 4
// speedup vs baseline: 2.8621x; 1.8615x over previous
#include <cuda_runtime.h>
#include <cuda_bf16.h>
#include <cstdint>

#define NB 4
#define NT 2048
#define ND 1024
#define NH 16
#define HD 64
#define QKV_N 3072

#define GM (NB * NT)   // 8192
#define GK 1024
#define BK 64
#define KIT (GK / BK)  // 16
#define TILE_B 16384
#define STAGE_B (4 * TILE_B)
#define GSMEM (2 * STAGE_B)

#define BH (NB * NH)        // 64
#define ASTAGE 32768        // K h/l + Vt h/l per stage
#define ATT_SMEM (32768 + 2 * ASTAGE)  // Q(32KB) + 2 stages

// ---------------- scratch (static device globals) ----------------
__device__ float g_qkv[(size_t)GM * QKV_N];
__device__ float g_y[(size_t)GM * ND];
__device__ __nv_bfloat16 g_ah[(size_t)GM * GK];
__device__ __nv_bfloat16 g_al[(size_t)GM * GK];
__device__ __nv_bfloat16 g_bh[(size_t)QKV_N * GK];
__device__ __nv_bfloat16 g_bl[(size_t)QKV_N * GK];
// attention operands
__device__ __nv_bfloat16 g_Qh[(size_t)BH * NT * HD];
__device__ __nv_bfloat16 g_Ql[(size_t)BH * NT * HD];
__device__ __nv_bfloat16 g_Kh[(size_t)BH * NT * HD];
__device__ __nv_bfloat16 g_Kl[(size_t)BH * NT * HD];
__device__ __nv_bfloat16 g_Vth[(size_t)BH * HD * NT];
__device__ __nv_bfloat16 g_Vtl[(size_t)BH * HD * NT];

// ---------------- PTX helpers (sm_80+ portable) ----------------
__device__ __forceinline__ uint32_t smem_u32(const void* p) {
    uint32_t a;
    asm("{ .reg .u64 t; cvta.to.shared.u64 t, %1; cvt.u32.u64 %0, t; }"
        : "=r"(a) : "l"(p));
    return a;
}
__device__ __forceinline__ void cp_async16(uint32_t dst, const void* src) {
    asm volatile("cp.async.cg.shared.global [%0], [%1], 16;"
                 :: "r"(dst), "l"(src) : "memory");
}
__device__ __forceinline__ void cp_commit() {
    asm volatile("cp.async.commit_group;" ::: "memory");
}
template <int N>
__device__ __forceinline__ void cp_wait() {
    asm volatile("cp.async.wait_group %0;" :: "n"(N) : "memory");
}
__device__ __forceinline__ void ldsm_x4(uint32_t* r, uint32_t addr) {
    asm volatile("ldmatrix.sync.aligned.m8n8.x4.shared.b16 {%0,%1,%2,%3}, [%4];"
                 : "=r"(r[0]), "=r"(r[1]), "=r"(r[2]), "=r"(r[3]) : "r"(addr));
}
__device__ __forceinline__ void mma_bf16(float* c, const uint32_t* a,
                                         const uint32_t* b) {
    asm volatile(
        "mma.sync.aligned.m16n8k16.row.col.f32.bf16.bf16.f32 "
        "{%0,%1,%2,%3}, {%4,%5,%6,%7}, {%8,%9}, {%0,%1,%2,%3};"
        : "+f"(c[0]), "+f"(c[1]), "+f"(c[2]), "+f"(c[3])
        : "r"(a[0]), "r"(a[1]), "r"(a[2]), "r"(a[3]), "r"(b[0]), "r"(b[1]));
}
__device__ __forceinline__ uint32_t pack_bf16(float lo, float hi) {
    uint32_t r;
    asm("cvt.rn.bf16x2.f32 %0, %1, %2;" : "=r"(r) : "f"(hi), "f"(lo));
    return r;
}
// split (x0,x1) into hi/lo bf16x2 packed regs
__device__ __forceinline__ void split_pair(float x0, float x1,
                                           uint32_t& h, uint32_t& l) {
    uint32_t hp = pack_bf16(x0, x1);
    float h0 = __uint_as_float(hp << 16);
    float h1 = __uint_as_float(hp & 0xffff0000u);
    l = pack_bf16(x0 - h0, x1 - h1);
    h = hp;
}
#define SWZ(x) ((uint32_t)(x) ^ ((((uint32_t)(x)) >> 3) & 0x70u))

// ---------------------------------------------------------------------------
// bf16x3 split GEMM via warp mma.sync (validated R3)
// ---------------------------------------------------------------------------
__global__ __launch_bounds__(256) void gemm3_kernel(
    const __nv_bfloat16* __restrict__ Ah, const __nv_bfloat16* __restrict__ Al,
    const __nv_bfloat16* __restrict__ Bh, const __nv_bfloat16* __restrict__ Bl,
    float* __restrict__ C, int M, int N, int K)
{
    extern __shared__ char smem[];
    const uint32_t sbase = smem_u32(smem);
    const int tid = threadIdx.x;
    const int wid = tid >> 5;
    const int lane = tid & 31;

    const int brow = blockIdx.y * 128;
    const int bcol = blockIdx.x * 128;
    const int wr = wid >> 2;
    const int wc = wid & 3;

    const int lrow = tid >> 1;
    const int lu4  = (tid & 1) * 4;

    const __nv_bfloat16* src[4];
    src[0] = Ah + (size_t)(brow + lrow) * K + lu4 * 8;
    src[1] = Al + (size_t)(brow + lrow) * K + lu4 * 8;
    src[2] = Bh + (size_t)(bcol + lrow) * K + lu4 * 8;
    src[3] = Bl + (size_t)(bcol + lrow) * K + lu4 * 8;

    uint32_t dsw[4];
#pragma unroll
    for (int q = 0; q < 4; q++)
        dsw[q] = SWZ(lrow * 128 + (lu4 + q) * 16);

    const int a_row_l = lane & 15;
    const int a_uoff  = lane >> 4;
    const int b_row_l = (lane & 7) + ((lane >> 4) & 1) * 8;
    const int b_uoff  = (lane >> 3) & 1;

    float acc[4][4][4] = {};

#pragma unroll
    for (int t = 0; t < 4; t++) {
        uint32_t dst = sbase + t * TILE_B;
#pragma unroll
        for (int q = 0; q < 4; q++)
            cp_async16(dst + dsw[q], src[t] + q * 8);
    }
    cp_commit();

    for (int it = 0; it < KIT; it++) {
        const int p = it & 1;
        if (it + 1 < KIT) {
            const uint32_t stg = sbase + (p ^ 1) * STAGE_B;
#pragma unroll
            for (int t = 0; t < 4; t++) {
                uint32_t dst = stg + t * TILE_B;
                const __nv_bfloat16* s = src[t] + (size_t)(it + 1) * BK;
#pragma unroll
                for (int q = 0; q < 4; q++)
                    cp_async16(dst + dsw[q], s + q * 8);
            }
            cp_commit();
            cp_wait<1>();
        } else {
            cp_wait<0>();
        }
        __syncthreads();

        const uint32_t sAh = sbase + p * STAGE_B;
        const uint32_t sAl = sAh + TILE_B;
        const uint32_t sBh = sAh + 2 * TILE_B;
        const uint32_t sBl = sAh + 3 * TILE_B;

#pragma unroll
        for (int ks = 0; ks < 4; ks++) {
            uint32_t ah[4][4], al[4][4];
#pragma unroll
            for (int mi = 0; mi < 4; mi++) {
                int row = wr * 64 + mi * 16 + a_row_l;
                uint32_t off = SWZ(row * 128 + (ks * 2 + a_uoff) * 16);
                ldsm_x4(ah[mi], sAh + off);
                ldsm_x4(al[mi], sAl + off);
            }
            uint32_t bh[4][2], bl[4][2];
#pragma unroll
            for (int np = 0; np < 2; np++) {
                int row = wc * 32 + np * 16 + b_row_l;
                uint32_t off = SWZ(row * 128 + (ks * 2 + b_uoff) * 16);
                uint32_t rh[4], rl[4];
                ldsm_x4(rh, sBh + off);
                ldsm_x4(rl, sBl + off);
                bh[np * 2][0] = rh[0]; bh[np * 2][1] = rh[1];
                bh[np * 2 + 1][0] = rh[2]; bh[np * 2 + 1][1] = rh[3];
                bl[np * 2][0] = rl[0]; bl[np * 2][1] = rl[1];
                bl[np * 2 + 1][0] = rl[2]; bl[np * 2 + 1][1] = rl[3];
            }
#pragma unroll
            for (int mi = 0; mi < 4; mi++)
#pragma unroll
                for (int ni = 0; ni < 4; ni++) {
                    mma_bf16(acc[mi][ni], ah[mi], bh[ni]);
                    mma_bf16(acc[mi][ni], ah[mi], bl[ni]);
                    mma_bf16(acc[mi][ni], al[mi], bh[ni]);
                }
        }
        __syncthreads();
    }

#pragma unroll
    for (int mi = 0; mi < 4; mi++) {
        int row0 = brow + wr * 64 + mi * 16 + (lane >> 2);
#pragma unroll
        for (int ni = 0; ni < 4; ni++) {
            int col = bcol + wc * 32 + ni * 8 + (lane & 3) * 2;
            float2* p0 = (float2*)&C[(size_t)row0 * N + col];
            float2* p1 = (float2*)&C[(size_t)(row0 + 8) * N + col];
            *p0 = make_float2(acc[mi][ni][0], acc[mi][ni][1]);
            *p1 = make_float2(acc[mi][ni][2], acc[mi][ni][3]);
        }
    }
}

// ---------------------------------------------------------------------------
// fp32 -> bf16 hi/lo split (elementwise)
// ---------------------------------------------------------------------------
__global__ __launch_bounds__(256) void split_kernel(
    const float* __restrict__ s, __nv_bfloat16* __restrict__ hi,
    __nv_bfloat16* __restrict__ lo, int n4)
{
    int i = blockIdx.x * 256 + threadIdx.x;
    if (i >= n4) return;
    float4 v = ((const float4*)s)[i];
    float f[4] = {v.x, v.y, v.z, v.w};
    __nv_bfloat16 h[4], l[4];
#pragma unroll
    for (int j = 0; j < 4; j++) {
        h[j] = __float2bfloat16(f[j]);
        l[j] = __float2bfloat16(f[j] - __bfloat162float(h[j]));
    }
    ((uint2*)hi)[i] = *(uint2*)h;
    ((uint2*)lo)[i] = *(uint2*)l;
}

// ---------------------------------------------------------------------------
// fp32 [K,N] -> bf16 hi/lo [N,K] split + transpose
// ---------------------------------------------------------------------------
__global__ __launch_bounds__(256) void split_transpose_kernel(
    const float* __restrict__ src, __nv_bfloat16* __restrict__ hi,
    __nv_bfloat16* __restrict__ lo, int K, int N)
{
    __shared__ float t[32][33];
    int k0 = blockIdx.y * 32, n0 = blockIdx.x * 32;
    int tx = threadIdx.x & 31, ty = threadIdx.x >> 5;
#pragma unroll
    for (int i = 0; i < 32; i += 8)
        t[ty + i][tx] = src[(size_t)(k0 + ty + i) * N + n0 + tx];
    __syncthreads();
#pragma unroll
    for (int i = 0; i < 32; i += 8) {
        float v = t[tx][ty + i];
        __nv_bfloat16 h = __float2bfloat16(v);
        size_t o = (size_t)(n0 + ty + i) * K + k0 + tx;
        hi[o] = h;
        lo[o] = __float2bfloat16(v - __bfloat162float(h));
    }
}

// ---------------------------------------------------------------------------
// Prep: qkv fp32 -> Qh/Ql (scaled 0.125), Kh/Kl in [bh, t, d] layout
// ---------------------------------------------------------------------------
__global__ __launch_bounds__(256) void qk_prep_kernel(
    const float* __restrict__ qkv,
    __nv_bfloat16* __restrict__ Qh, __nv_bfloat16* __restrict__ Ql,
    __nv_bfloat16* __restrict__ Kh, __nv_bfloat16* __restrict__ Kl)
{
    int i = blockIdx.x * 256 + threadIdx.x;   // over GM * 256
    int d4 = i & 255;
    int bt = i >> 8;
    int h = d4 >> 4;
    int dd = (d4 & 15) * 4;
    int b = bt >> 11;
    int t = bt & 2047;

    size_t src = (size_t)bt * QKV_N + d4 * 4;
    float4 q = *(const float4*)&qkv[src];
    float4 k = *(const float4*)&qkv[src + ND];
    size_t dst = (((size_t)(b * NH + h)) * NT + t) * HD + dd;

    float fq[4] = {q.x * 0.125f, q.y * 0.125f, q.z * 0.125f, q.w * 0.125f};
    float fk[4] = {k.x, k.y, k.z, k.w};
    __nv_bfloat16 hq[4], lq[4], hk[4], lk[4];
#pragma unroll
    for (int j = 0; j < 4; j++) {
        hq[j] = __float2bfloat16(fq[j]);
        lq[j] = __float2bfloat16(fq[j] - __bfloat162float(hq[j]));
        hk[j] = __float2bfloat16(fk[j]);
        lk[j] = __float2bfloat16(fk[j] - __bfloat162float(hk[j]));
    }
    *(uint2*)&Qh[dst] = *(uint2*)hq;
    *(uint2*)&Ql[dst] = *(uint2*)lq;
    *(uint2*)&Kh[dst] = *(uint2*)hk;
    *(uint2*)&Kl[dst] = *(uint2*)lk;
}

// ---------------------------------------------------------------------------
// Prep: V fp32 [t, d] -> Vt bf16 hi/lo [bh, d, t] (32x32 smem transpose)
// ---------------------------------------------------------------------------
__global__ __launch_bounds__(256) void v_prep_kernel(
    const float* __restrict__ qkv,
    __nv_bfloat16* __restrict__ Vth, __nv_bfloat16* __restrict__ Vtl)
{
    __shared__ float tb[32][33];
    int d0 = blockIdx.x * 32, t0 = blockIdx.y * 32, bh = blockIdx.z;
    int b = bh >> 4, h = bh & 15;
    int tx = threadIdx.x & 31, ty = threadIdx.x >> 5;
#pragma unroll
    for (int i = 0; i < 32; i += 8)
        tb[ty + i][tx] = qkv[((size_t)(b * NT) + t0 + ty + i) * QKV_N +
                             2 * ND + h * HD + d0 + tx];
    __syncthreads();
#pragma unroll
    for (int i = 0; i < 32; i += 8) {
        float v = tb[tx][ty + i];
        __nv_bfloat16 hh = __float2bfloat16(v);
        size_t o = ((size_t)bh * HD + d0 + ty + i) * NT + t0 + tx;
        Vth[o] = hh;
        Vtl[o] = __float2bfloat16(v - __bfloat162float(hh));
    }
}

// ---------------------------------------------------------------------------
// Tensor-core flash attention (bf16x3, causal).
// CTA = 128 q rows x one (b,h). 8 warps, each 16 q rows x 64-wide kv tiles.
// Double-buffered cp.async K/V stages; Q fragments hoisted to registers.
// ---------------------------------------------------------------------------
__global__ __launch_bounds__(256) void fattn_kernel(
    const __nv_bfloat16* __restrict__ Qh, const __nv_bfloat16* __restrict__ Ql,
    const __nv_bfloat16* __restrict__ Kh, const __nv_bfloat16* __restrict__ Kl,
    const __nv_bfloat16* __restrict__ Vth, const __nv_bfloat16* __restrict__ Vtl,
    float* __restrict__ y)
{
    extern __shared__ char smem[];
    const uint32_t sb = smem_u32(smem);
    const int tid = threadIdx.x;
    const int wid = tid >> 5;
    const int lane = tid & 31;
    const int qt = 15 - blockIdx.x;    // descending work order
    const int bh = blockIdx.y;

    const uint32_t sQh = 0, sQl = 16384, stg0 = 32768;
    // stage layout: Kh @0, Kl @8192, Vth @16384, Vtl @24576

    // ---- issue Q loads (group 0) ----
    {
        int row = tid >> 1;
        int u0 = (tid & 1) * 4;
        size_t g = ((size_t)bh * NT + qt * 128 + row) * HD + u0 * 8;
#pragma unroll
        for (int q = 0; q < 4; q++) {
            uint32_t d = SWZ(row * 128 + (u0 + q) * 16);
            cp_async16(sb + sQh + d, Qh + g + q * 8);
            cp_async16(sb + sQl + d, Ql + g + q * 8);
        }
    }
    cp_commit();

    // ---- kv stage loader ----
    const int kv_row = tid >> 2;
    const int kv_u0 = (tid & 3) * 2;
    const uint32_t kv_o0 = SWZ(kv_row * 128 + kv_u0 * 16);
    const uint32_t kv_o1 = SWZ(kv_row * 128 + (kv_u0 + 1) * 16);

    auto issue_kv = [&](int j, int s) {
        uint32_t st = sb + stg0 + s * ASTAGE;
        size_t gk = ((size_t)bh * NT + j * 64 + kv_row) * HD + kv_u0 * 8;
        size_t gv = ((size_t)bh * HD + kv_row) * NT + (size_t)j * 64 + kv_u0 * 8;
        cp_async16(st + kv_o0, Kh + gk);
        cp_async16(st + kv_o1, Kh + gk + 8);
        cp_async16(st + 8192 + kv_o0, Kl + gk);
        cp_async16(st + 8192 + kv_o1, Kl + gk + 8);
        cp_async16(st + 16384 + kv_o0, Vth + gv);
        cp_async16(st + 16384 + kv_o1, Vth + gv + 8);
        cp_async16(st + 24576 + kv_o0, Vtl + gv);
        cp_async16(st + 24576 + kv_o1, Vtl + gv + 8);
    };

    issue_kv(0, 0);
    cp_commit();

    // ---- Q fragments to registers ----
    cp_wait<1>();   // Q group done
    __syncthreads();

    const int a_row = wid * 16 + (lane & 15);
    const int a_u = lane >> 4;
    uint32_t qh[4][4], ql[4][4];
#pragma unroll
    for (int ks = 0; ks < 4; ks++) {
        uint32_t off = SWZ(a_row * 128 + (ks * 2 + a_u) * 16);
        ldsm_x4(qh[ks], sb + sQh + off);
        ldsm_x4(ql[ks], sb + sQl + off);
    }

    const int b_row = (lane & 7) + ((lane >> 4) & 1) * 8;
    const int b_u = (lane >> 3) & 1;

    float O[8][4] = {};
    float m0 = -1e30f, m1 = -1e30f, l0 = 0.f, l1 = 0.f;

    const int jmax = 2 * qt + 2;
    const int q0g = qt * 128 + wid * 16 + (lane >> 2);

    for (int j = 0; j < jmax; j++) {
        const int p = j & 1;
        if (j + 1 < jmax) {
            issue_kv(j + 1, p ^ 1);
            cp_commit();
            cp_wait<1>();
        } else {
            cp_wait<0>();
        }
        __syncthreads();

        const uint32_t sK = sb + stg0 + p * ASTAGE;

        // ---- S = Q K^T (3-term) ----
        float s[8][4] = {};
#pragma unroll
        for (int ks = 0; ks < 4; ks++) {
#pragma unroll
            for (int g = 0; g < 4; g++) {
                uint32_t off = SWZ((g * 16 + b_row) * 128 + (ks * 2 + b_u) * 16);
                uint32_t kbh[4], kbl[4];
                ldsm_x4(kbh, sK + off);
                ldsm_x4(kbl, sK + 8192 + off);
                mma_bf16(s[2 * g], qh[ks], kbh);
                mma_bf16(s[2 * g], qh[ks], kbl);
                mma_bf16(s[2 * g], ql[ks], kbh);
                mma_bf16(s[2 * g + 1], qh[ks], kbh + 2);
                mma_bf16(s[2 * g + 1], qh[ks], kbl + 2);
                mma_bf16(s[2 * g + 1], ql[ks], kbh + 2);
            }
        }

        // ---- causal mask (only diagonal tiles) ----
        if (j >= 2 * qt) {
            int kvb = j * 64 + (lane & 3) * 2;
#pragma unroll
            for (int f = 0; f < 8; f++) {
                int kv = kvb + f * 8;
                if (kv > q0g)     s[f][0] = -1e30f;
                if (kv + 1 > q0g) s[f][1] = -1e30f;
                if (kv > q0g + 8)     s[f][2] = -1e30f;
                if (kv + 1 > q0g + 8) s[f][3] = -1e30f;
            }
        }

        // ---- online softmax (within warp) ----
        float mx0 = -1e30f, mx1 = -1e30f;
#pragma unroll
        for (int f = 0; f < 8; f++) {
            mx0 = fmaxf(mx0, fmaxf(s[f][0], s[f][1]));
            mx1 = fmaxf(mx1, fmaxf(s[f][2], s[f][3]));
        }
        mx0 = fmaxf(mx0, __shfl_xor_sync(0xffffffffu, mx0, 1));
        mx0 = fmaxf(mx0, __shfl_xor_sync(0xffffffffu, mx0, 2));
        mx1 = fmaxf(mx1, __shfl_xor_sync(0xffffffffu, mx1, 1));
        mx1 = fmaxf(mx1, __shfl_xor_sync(0xffffffffu, mx1, 2));

        float mn0 = fmaxf(m0, mx0), mn1 = fmaxf(m1, mx1);
        float al0 = __expf(m0 - mn0), al1 = __expf(m1 - mn1);

        float sum0 = 0.f, sum1 = 0.f;
#pragma unroll
        for (int f = 0; f < 8; f++) {
            s[f][0] = __expf(s[f][0] - mn0);
            s[f][1] = __expf(s[f][1] - mn0);
            s[f][2] = __expf(s[f][2] - mn1);
            s[f][3] = __expf(s[f][3] - mn1);
            sum0 += s[f][0] + s[f][1];
            sum1 += s[f][2] + s[f][3];
        }
        sum0 += __shfl_xor_sync(0xffffffffu, sum0, 1);
        sum0 += __shfl_xor_sync(0xffffffffu, sum0, 2);
        sum1 += __shfl_xor_sync(0xffffffffu, sum1, 1);
        sum1 += __shfl_xor_sync(0xffffffffu, sum1, 2);

        m0 = mn0; m1 = mn1;
        l0 = l0 * al0 + sum0;
        l1 = l1 * al1 + sum1;

#pragma unroll
        for (int f = 0; f < 8; f++) {
            O[f][0] *= al0; O[f][1] *= al0;
            O[f][2] *= al1; O[f][3] *= al1;
        }

        // ---- O += P V (3-term, P split in registers) ----
#pragma unroll
        for (int kk = 0; kk < 4; kk++) {
            uint32_t ph[4], pl[4];
            split_pair(s[2 * kk][0], s[2 * kk][1], ph[0], pl[0]);
            split_pair(s[2 * kk][2], s[2 * kk][3], ph[1], pl[1]);
            split_pair(s[2 * kk + 1][0], s[2 * kk + 1][1], ph[2], pl[2]);
            split_pair(s[2 * kk + 1][2], s[2 * kk + 1][3], ph[3], pl[3]);
#pragma unroll
            for (int g = 0; g < 4; g++) {
                uint32_t off = SWZ((g * 16 + b_row) * 128 + (kk * 2 + b_u) * 16);
                uint32_t vh[4], vl[4];
                ldsm_x4(vh, sK + 16384 + off);
                ldsm_x4(vl, sK + 24576 + off);
                mma_bf16(O[2 * g], ph, vh);
                mma_bf16(O[2 * g], ph, vl);
                mma_bf16(O[2 * g], pl, vh);
                mma_bf16(O[2 * g + 1], ph, vh + 2);
                mma_bf16(O[2 * g + 1], ph, vl + 2);
                mma_bf16(O[2 * g + 1], pl, vh + 2);
            }
        }
        __syncthreads();
    }

    // ---- epilogue: y[b, t, h*64 + d] ----
    float i0 = 1.f / l0, i1 = 1.f / l1;
    int b = bh >> 4, h = bh & 15;
    size_t base = ((size_t)b * NT + q0g) * ND + h * HD + (lane & 3) * 2;
#pragma unroll
    for (int f = 0; f < 8; f++) {
        *(float2*)&y[base + f * 8] = make_float2(O[f][0] * i0, O[f][1] * i0);
        *(float2*)&y[base + (size_t)8 * ND + f * 8] =
            make_float2(O[f][2] * i1, O[f][3] * i1);
    }
}

// ---------------------------------------------------------------------------
extern "C" void kernel_launch(void* const* d_in, const int* in_sizes, int n_in,
                              void* d_out, int out_size)
{
    const float* x     = (const float*)d_in[0];
    const float* w_qkv = (const float*)d_in[1];
    const float* w_out = (const float*)d_in[2];
    float* out = (float*)d_out;

    float *qkv, *yb;
    __nv_bfloat16 *ah, *al, *bh, *bl, *Qh, *Ql, *Kh, *Kl, *Vth, *Vtl;
    cudaGetSymbolAddress((void**)&qkv, g_qkv);
    cudaGetSymbolAddress((void**)&yb, g_y);
    cudaGetSymbolAddress((void**)&ah, g_ah);
    cudaGetSymbolAddress((void**)&al, g_al);
    cudaGetSymbolAddress((void**)&bh, g_bh);
    cudaGetSymbolAddress((void**)&bl, g_bl);
    cudaGetSymbolAddress((void**)&Qh, g_Qh);
    cudaGetSymbolAddress((void**)&Ql, g_Ql);
    cudaGetSymbolAddress((void**)&Kh, g_Kh);
    cudaGetSymbolAddress((void**)&Kl, g_Kl);
    cudaGetSymbolAddress((void**)&Vth, g_Vth);
    cudaGetSymbolAddress((void**)&Vtl, g_Vtl);

    cudaFuncSetAttribute(gemm3_kernel, cudaFuncAttributeMaxDynamicSharedMemorySize,
                         GSMEM);
    cudaFuncSetAttribute(fattn_kernel, cudaFuncAttributeMaxDynamicSharedMemorySize,
                         ATT_SMEM);

    const int n4 = GM * GK / 4;

    // 1) split x, split+transpose w_qkv
    split_kernel<<<(n4 + 255) / 256, 256>>>(x, ah, al, n4);
    split_transpose_kernel<<<dim3(QKV_N / 32, GK / 32), 256>>>(w_qkv, bh, bl, GK, QKV_N);

    // 2) qkv = x @ w_qkv
    gemm3_kernel<<<dim3(QKV_N / 128, GM / 128), 256, GSMEM>>>(
        ah, al, bh, bl, qkv, GM, QKV_N, GK);

    // 3) prep attention operands
    qk_prep_kernel<<<GM, 256>>>(qkv, Qh, Ql, Kh, Kl);
    v_prep_kernel<<<dim3(HD / 32, NT / 32, BH), 256>>>(qkv, Vth, Vtl);

    // 4) tensor-core flash attention -> y
    fattn_kernel<<<dim3(NT / 128, BH), 256, ATT_SMEM>>>(
        Qh, Ql, Kh, Kl, Vth, Vtl, yb);

    // 5) split y, split+transpose w_out
    split_kernel<<<(n4 + 255) / 256, 256>>>(yb, ah, al, n4);
    split_transpose_kernel<<<dim3(ND / 32, GK / 32), 256>>>(w_out, bh, bl, GK, ND);

    // 6) out = y @ w_out
    gemm3_kernel<<<dim3(ND / 128, GM / 128), 256, GSMEM>>>(
        ah, al, bh, bl, out, GM, ND, GK);
}